// round 2
// baseline (speedup 1.0000x reference)
#include <cuda_runtime.h>
#include <math.h>

// Problem constants
#define FDIM 221
#define BATCH 2048
#define XS 224              // padded x row stride
#define NP 256              // padded N (output features) for the GEMM
#define DDIM 13
#define SDIM 26
#define EDIM 8
#define VDIM 100000
#define TRI 24531           // F*(F+1)/2 upper-triangle pairs
#define TRIP 24544          // padded to multiple of BK
#define BK 16
#define BM 64
#define CHUNKS (TRIP / BK)  // 1534
#define KSPLIT 8
#define CPS ((CHUNKS + KSPLIT - 1) / KSPLIT)  // 192

// ---- scratch (device globals; no allocation APIs) ----
__device__ float d_X1[BATCH * XS];
__device__ float d_X2[BATCH * XS];
__device__ float d_Wp1[(size_t)TRIP * NP];
__device__ float d_Wp2[(size_t)TRIP * NP];
__device__ float d_Yp[(size_t)KSPLIT * BATCH * XS];
__device__ int   d_Ti[TRIP];
__device__ int   d_Tj[TRIP];

// ---- f32x2 helpers ----
__device__ __forceinline__ unsigned long long pack2f(float x) {
    unsigned long long r;
    asm("mov.b64 %0, {%1, %1};" : "=l"(r) : "f"(x));
    return r;
}
__device__ __forceinline__ void fma2(unsigned long long& acc,
                                     unsigned long long a,
                                     unsigned long long b) {
    asm("fma.rn.f32x2 %0, %1, %2, %0;" : "+l"(acc) : "l"(a), "l"(b));
}
__device__ __forceinline__ float2 unpack2f(unsigned long long v) {
    float2 f;
    asm("mov.b64 {%0, %1}, %2;" : "=f"(f.x), "=f"(f.y) : "l"(v));
    return f;
}

// ---- 1) triangular pair index tables ----
__global__ void make_pairs_kernel() {
    int tid = threadIdx.x;
    for (int i = tid; i < FDIM; i += blockDim.x) {
        int start = i * FDIM - (i * (i - 1)) / 2;
        for (int j = i; j < FDIM; j++) {
            d_Ti[start + j - i] = i;
            d_Tj[start + j - i] = j;
        }
    }
    for (int r = TRI + tid; r < TRIP; r += blockDim.x) {
        d_Ti[r] = 0; d_Tj[r] = 0;
    }
}

// ---- 2) fold W into symmetric packed form: Wp[r,k] = W[ij,k] + W[ji,k] (i<j), W[ii,k] on diag ----
template <int L>
__global__ void pack_kernel(const float* __restrict__ W) {
    float* Wp = (L == 0) ? d_Wp1 : d_Wp2;
    int r = blockIdx.x;
    float* dst = Wp + (size_t)r * NP;
    if (r >= TRI) {
        for (int c = threadIdx.x; c < NP; c += blockDim.x) dst[c] = 0.f;
        return;
    }
    int i = d_Ti[r], j = d_Tj[r];
    const float* wa = W + ((size_t)i * FDIM + j) * FDIM;
    const float* wb = W + ((size_t)j * FDIM + i) * FDIM;
    for (int c = threadIdx.x; c < NP; c += blockDim.x) {
        float v = 0.f;
        if (c < FDIM) {
            v = wa[c];
            if (i != j) v += wb[c];
        }
        dst[c] = v;
    }
}

// ---- 3) build x = [dense | embeddings], padded to 224 cols ----
__global__ void build_x_kernel(const float* __restrict__ dense,
                               const int* __restrict__ sparse,
                               const float* __restrict__ emb) {
    int b = blockIdx.x;
    int t = threadIdx.x;
    float v = 0.f;
    if (t < DDIM) {
        v = dense[b * DDIM + t];
    } else if (t < FDIM) {
        int q = t - DDIM;
        int s = q >> 3;
        int e = q & 7;
        int idx = sparse[b * SDIM + s];
        v = emb[((size_t)s * VDIM + idx) * EDIM + e];
    }
    d_X1[b * XS + t] = v;
}

// ---- 4) interaction GEMM: Yp[split][b][k] = sum over this split's K-rows of (x_i x_j) * Wp[r,k] ----
// L=0: X1 x Wp1 ; L=1: X2 x Wp2.  Grid: (BATCH/BM, KSPLIT), 256 threads.
template <int L>
__global__ void __launch_bounds__(256, 2) interact_gemm_kernel() {
    const float* __restrict__ X  = (L == 0) ? d_X1 : d_X2;
    const float* __restrict__ Wp = (L == 0) ? d_Wp1 : d_Wp2;

    __shared__ __align__(16) float Ws[2][BK][NP];  // 32 KB
    __shared__ __align__(16) float As[2][BK][BM];  // 8 KB

    const int tid   = threadIdx.x;
    const int mBase = blockIdx.x * BM;
    const int split = blockIdx.y;
    const int c0 = split * CPS;
    const int c1 = min(c0 + CPS, CHUNKS);
    const int colg = tid & 31;   // cols: colg*2 + s*64  (4 float2 pairs)
    const int rowg = tid >> 5;   // rows: rowg*8 .. rowg*8+7

    unsigned long long acc[8][4];
#pragma unroll
    for (int a = 0; a < 8; a++)
#pragma unroll
        for (int s = 0; s < 4; s++) acc[a][s] = 0ULL;

    auto issueW = [&](int buf, int chunk) {
        const float* src = Wp + (size_t)chunk * (BK * NP);
#pragma unroll
        for (int t = 0; t < 4; t++) {
            int e  = tid + t * 256;       // 0..1023 = 16 rows * 64 float4
            int kk = e >> 6;
            int c4 = (e & 63) << 2;
            unsigned sm = (unsigned)__cvta_generic_to_shared(&Ws[buf][kk][c4]);
            asm volatile("cp.async.cg.shared.global [%0], [%1], 16;\n"
                         :: "r"(sm), "l"(src + kk * NP + c4));
        }
        asm volatile("cp.async.commit_group;\n");
    };
    auto buildA = [&](int buf, int chunk) {
#pragma unroll
        for (int t = 0; t < 4; t++) {
            int e  = tid + t * 256;
            int kk = e >> 6;
            int m  = e & 63;
            int r  = chunk * BK + kk;
            int i  = __ldg(&d_Ti[r]);
            int j  = __ldg(&d_Tj[r]);
            const float* xr = X + (size_t)(mBase + m) * XS;
            As[buf][kk][m] = __ldg(xr + i) * __ldg(xr + j);
        }
    };

    issueW(0, c0);
    buildA(0, c0);
    asm volatile("cp.async.wait_group 0;\n");
    __syncthreads();

    for (int ch = c0; ch < c1; ch++) {
        const int buf = (ch - c0) & 1;
        const bool hasNext = (ch + 1 < c1);
        if (hasNext) {
            issueW(buf ^ 1, ch + 1);   // async, overlaps FMAs below
            buildA(buf ^ 1, ch + 1);   // LDG->STS into the other buffer
        }
#pragma unroll
        for (int kk = 0; kk < BK; kk++) {
            const float4 a0 = *reinterpret_cast<const float4*>(&As[buf][kk][rowg * 8]);
            const float4 a1 = *reinterpret_cast<const float4*>(&As[buf][kk][rowg * 8 + 4]);
            unsigned long long ap[8];
            ap[0] = pack2f(a0.x); ap[1] = pack2f(a0.y);
            ap[2] = pack2f(a0.z); ap[3] = pack2f(a0.w);
            ap[4] = pack2f(a1.x); ap[5] = pack2f(a1.y);
            ap[6] = pack2f(a1.z); ap[7] = pack2f(a1.w);
            unsigned long long wv[4];
#pragma unroll
            for (int s = 0; s < 4; s++)
                wv[s] = *reinterpret_cast<const unsigned long long*>(
                    &Ws[buf][kk][colg * 2 + s * 64]);
#pragma unroll
            for (int tm = 0; tm < 8; tm++)
#pragma unroll
                for (int s = 0; s < 4; s++)
                    fma2(acc[tm][s], ap[tm], wv[s]);
        }
        if (hasNext) asm volatile("cp.async.wait_group 0;\n");
        __syncthreads();
    }

    // deterministic per-split partial store (coalesced float2)
#pragma unroll
    for (int tm = 0; tm < 8; tm++) {
        const int row = mBase + rowg * 8 + tm;
        float* dst = d_Yp + ((size_t)split * BATCH + row) * XS;
#pragma unroll
        for (int s = 0; s < 4; s++) {
            int col = colg * 2 + s * 64;
            if (col < XS) {  // s<3 always; s==3 only colg<16
                float2 v = unpack2f(acc[tm][s]);
                *reinterpret_cast<float2*>(dst + col) = v;
            }
        }
    }
}

// ---- 5) reduce split-K partials + bias -> X2 (zero-padded) ----
__global__ void reduce1_kernel(const float* __restrict__ b1) {
    int b = blockIdx.x;
    int c = threadIdx.x;
    float v = 0.f;
    if (c < FDIM) {
        v = b1[c];
#pragma unroll
        for (int p = 0; p < KSPLIT; p++)
            v += d_Yp[((size_t)p * BATCH + b) * XS + c];
    }
    d_X2[b * XS + c] = v;
}

// ---- 6) final: reduce split-K partials of layer2 + bias, row-sum (softmax over size-1 axis == 1), sigmoid ----
__global__ void final_kernel(const float* __restrict__ b2,
                             const float* __restrict__ out_w,
                             const float* __restrict__ out_b,
                             float* __restrict__ out) {
    int warp = threadIdx.x >> 5;
    int lane = threadIdx.x & 31;
    int b = blockIdx.x * 8 + warp;
    float sum = 0.f;
    for (int c = lane; c < FDIM; c += 32) {
        float t = b2[c];
#pragma unroll
        for (int p = 0; p < KSPLIT; p++)
            t += d_Yp[((size_t)p * BATCH + b) * XS + c];
        sum += t;
    }
#pragma unroll
    for (int o = 16; o > 0; o >>= 1) sum += __shfl_down_sync(0xffffffffu, sum, o);
    if (lane == 0) {
        float z = sum * out_w[0] + out_b[0];
        out[b] = 1.f / (1.f + expf(-z));
    }
}

extern "C" void kernel_launch(void* const* d_in, const int* in_sizes, int n_in,
                              void* d_out, int out_size) {
    const float* dense  = (const float*)d_in[0];
    const int*   sparse = (const int*)  d_in[1];
    const float* emb    = (const float*)d_in[2];
    const float* W1     = (const float*)d_in[3];
    const float* b1     = (const float*)d_in[4];
    const float* W2     = (const float*)d_in[5];
    const float* b2     = (const float*)d_in[6];
    // d_in[7..10]: attention weights — mathematically dead (softmax over a size-1 axis is 1)
    const float* out_w  = (const float*)d_in[11];
    const float* out_b  = (const float*)d_in[12];
    float* out = (float*)d_out;

    make_pairs_kernel<<<1, 256>>>();
    pack_kernel<0><<<TRIP, 64>>>(W1);
    pack_kernel<1><<<TRIP, 64>>>(W2);
    build_x_kernel<<<BATCH, XS>>>(dense, sparse, emb);

    dim3 ggrid(BATCH / BM, KSPLIT);
    interact_gemm_kernel<0><<<ggrid, 256>>>();
    reduce1_kernel<<<BATCH, XS>>>(b1);
    interact_gemm_kernel<1><<<ggrid, 256>>>();
    final_kernel<<<BATCH / 8, 256>>>(b2, out_w, out_b, out);
}